// round 1
// baseline (speedup 1.0000x reference)
#include <cuda_runtime.h>
#include <cuda_bf16.h>

// Problem constants
#define BATCH 4
#define DD 160
#define HH 192
#define WW 224
// centers: (shape-1)/2
#define CD 79.5f
#define CH 95.5f
#define CW 111.5f

// Groups: each thread handles 12 consecutive floats = 4 w-positions x 3 channels
// Total floats = 4*160*192*224*3 = 82,575,360 ; groups = 6,881,280
#define WGROUPS (WW / 4)              // 56 groups per row
#define TOTAL_GROUPS (BATCH * DD * HH * WGROUPS)

__global__ __launch_bounds__(256)
void affine_shift_kernel(const float* __restrict__ mat, float4* __restrict__ out4) {
    unsigned g = blockIdx.x * 256u + threadIdx.x;
    // exact grid, no bounds check needed (grid chosen so g < TOTAL_GROUPS)

    // Decompose group index: g = ((b*DD + d)*HH + h)*WGROUPS + wq
    unsigned wq = g % WGROUPS;
    unsigned r  = g / WGROUPS;
    unsigned h  = r % HH;
    unsigned t  = r / HH;
    unsigned d  = t % DD;
    unsigned b  = t / DD;

    // Load matrix rows for batch b: [3,4] row-major, 48B aligned (b*12 floats)
    const float4* m4 = reinterpret_cast<const float4*>(mat) + b * 3;
    float4 r0 = m4[0];  // a00 a01 a02 t0
    float4 r1 = m4[1];  // a10 a11 a12 t1
    float4 r2 = m4[2];  // a20 a21 a22 t2

    float dp = (float)d - CD;
    float hp = (float)h - CH;
    float wp = (float)(4u * wq) - CW;

    // out_c = (A - I)[c,:] . (dp,hp,wp) + t_c
    float base0 = fmaf(r0.x - 1.0f, dp, fmaf(r0.y, hp, r0.w));
    float base1 = fmaf(r1.x,        dp, fmaf(r1.y - 1.0f, hp, r1.w));
    float base2 = fmaf(r2.x,        dp, fmaf(r2.y, hp, r2.w));
    float wc0 = r0.z;
    float wc1 = r1.z;
    float wc2 = r2.z - 1.0f;

    float w0 = wp;
    float w1 = wp + 1.0f;
    float w2 = wp + 2.0f;
    float w3 = wp + 3.0f;

    float4 o0, o1, o2;
    o0.x = fmaf(wc0, w0, base0);
    o0.y = fmaf(wc1, w0, base1);
    o0.z = fmaf(wc2, w0, base2);
    o0.w = fmaf(wc0, w1, base0);

    o1.x = fmaf(wc1, w1, base1);
    o1.y = fmaf(wc2, w1, base2);
    o1.z = fmaf(wc0, w2, base0);
    o1.w = fmaf(wc1, w2, base1);

    o2.x = fmaf(wc2, w2, base2);
    o2.y = fmaf(wc0, w3, base0);
    o2.z = fmaf(wc1, w3, base1);
    o2.w = fmaf(wc2, w3, base2);

    float4* p = out4 + (size_t)g * 3;
    p[0] = o0;
    p[1] = o1;
    p[2] = o2;
}

extern "C" void kernel_launch(void* const* d_in, const int* in_sizes, int n_in,
                              void* d_out, int out_size) {
    const float* mat = (const float*)d_in[0];
    float4* out4 = (float4*)d_out;
    // TOTAL_GROUPS = 6,881,280 = 26,880 * 256  (exact)
    dim3 grid(TOTAL_GROUPS / 256);
    affine_shift_kernel<<<grid, 256>>>(mat, out4);
}

// round 2
// speedup vs baseline: 1.0750x; 1.0750x over previous
#include <cuda_runtime.h>
#include <cuda_bf16.h>

// Problem constants
#define BATCH 4
#define DD 160
#define HH 192
#define WW 224
#define CD 79.5f
#define CH 95.5f
#define CW 111.5f

// Output: [B, D, H, W, 3] f32 = 82,575,360 floats = 20,643,840 float4
// One row (fixed b,d,h) = 224*3 = 672 floats = 168 float4  (no float4 crosses a row)
#define ROW_F4 168
#define TOTAL_F4 (BATCH * DD * HH * ROW_F4)   // 20,643,840 = 80,640 * 256

__global__ __launch_bounds__(256)
void affine_shift_kernel(const float* __restrict__ mat, float4* __restrict__ out4) {
    unsigned i = blockIdx.x * 256u + threadIdx.x;   // float4 index; grid exact

    // Decompose: i = rowi * ROW_F4 + ri ; rowi = (b*DD + d)*HH + h
    unsigned ri   = i % ROW_F4;
    unsigned rowi = i / ROW_F4;
    unsigned h    = rowi % HH;
    unsigned t    = rowi / HH;
    unsigned d    = t % DD;
    unsigned b    = t / DD;

    unsigned fr = 4u * ri;        // float offset within row [0,672)
    unsigned w0 = fr / 3u;        // first spatial w in this float4
    unsigned c0 = fr % 3u;        // channel of first float

    // Matrix rows for batch b (uniform per warp -> L1 hit)
    const float4* m4 = reinterpret_cast<const float4*>(mat) + b * 3;
    float4 r0 = m4[0];  // a00 a01 a02 t0
    float4 r1 = m4[1];  // a10 a11 a12 t1
    float4 r2 = m4[2];  // a20 a21 a22 t2

    float dp = (float)d - CD;
    float hp = (float)h - CH;
    float wp = (float)w0 - CW;

    // out_c(w) = base_c + wc_c * (w - CW)
    float base0 = fmaf(r0.x - 1.0f, dp, fmaf(r0.y, hp, r0.w));
    float base1 = fmaf(r1.x,        dp, fmaf(r1.y - 1.0f, hp, r1.w));
    float base2 = fmaf(r2.x,        dp, fmaf(r2.y, hp, r2.w));
    float wc0 = r0.z;
    float wc1 = r1.z;
    float wc2 = r2.z - 1.0f;

    float v[4];
#pragma unroll
    for (int j = 0; j < 4; j++) {
        unsigned cj = c0 + (unsigned)j;          // [0,5]
        float w = wp;
        if (cj >= 3u) { cj -= 3u; w += 1.0f; }   // -> SEL/predicated, no divergence
        float bsel  = (cj == 0u) ? base0 : ((cj == 1u) ? base1 : base2);
        float wcsel = (cj == 0u) ? wc0   : ((cj == 1u) ? wc1   : wc2);
        v[j] = fmaf(wcsel, w, bsel);
    }

    out4[i] = make_float4(v[0], v[1], v[2], v[3]);
}

extern "C" void kernel_launch(void* const* d_in, const int* in_sizes, int n_in,
                              void* d_out, int out_size) {
    const float* mat = (const float*)d_in[0];
    float4* out4 = (float4*)d_out;
    // TOTAL_F4 = 20,643,840 = 80,640 * 256 (exact)
    affine_shift_kernel<<<TOTAL_F4 / 256, 256>>>(mat, out4);
}

// round 3
// speedup vs baseline: 1.7205x; 1.6004x over previous
#include <cuda_runtime.h>
#include <cuda_bf16.h>

// Problem: out[b,d,h,w,c] = (A-I)[c,:] . (d-CD, h-CH, w-CW) + t_c
// Shapes: B=4, D=160, H=192, W=224, C=3 -> 82,575,360 f32 (330 MB, store-bound)
#define BATCH 4
#define DD 160
#define HH 192
#define WW 224
#define CD 79.5f
#define CH 95.5f
#define CW 111.5f

// One row = 224*3 = 672 floats = 168 float4.
// Block = 224 threads, covers 4 whole rows = 2688 floats = 672 float4.
// Thread t computes 12 contiguous floats (4 w, channels 0,1,2 fixed pattern).
#define THREADS 224
#define ROWS_PER_BLK 4
#define ROW_FLOATS (WW * 3)           // 672
#define BLK_F4 (ROWS_PER_BLK * ROW_FLOATS / 4)   // 672 float4 per block
#define TOTAL_ROWS (BATCH * DD * HH)  // 122,880
#define NBLOCKS (TOTAL_ROWS / ROWS_PER_BLK)      // 30,720

__global__ __launch_bounds__(THREADS)
void affine_shift_kernel(const float* __restrict__ mat, float4* __restrict__ out4) {
    __shared__ float4 s[BLK_F4];      // 10.75 KB

    unsigned t = threadIdx.x;

    // ---- Phase 1: compute 12 floats with fixed channel pattern ----
    unsigned tr = t / 56u;            // local row 0..3   (56 threads per row)
    unsigned tw = t - tr * 56u;       // position within row, w0 = 4*tw

    unsigned R = blockIdx.x * ROWS_PER_BLK + tr;   // global row
    unsigned h = R % HH;
    unsigned q = R / HH;
    unsigned d = q % DD;
    unsigned b = q / DD;

    const float4* m4 = reinterpret_cast<const float4*>(mat) + b * 3;
    float4 r0 = m4[0];  // a00 a01 a02 t0
    float4 r1 = m4[1];  // a10 a11 a12 t1
    float4 r2 = m4[2];  // a20 a21 a22 t2

    float dp = (float)d - CD;
    float hp = (float)h - CH;
    float wp = (float)(4u * tw) - CW;

    float base0 = fmaf(r0.x - 1.0f, dp, fmaf(r0.y, hp, r0.w));
    float base1 = fmaf(r1.x,        dp, fmaf(r1.y - 1.0f, hp, r1.w));
    float base2 = fmaf(r2.x,        dp, fmaf(r2.y, hp, r2.w));
    float wc0 = r0.z;
    float wc1 = r1.z;
    float wc2 = r2.z - 1.0f;

    float w0 = wp, w1 = wp + 1.0f, w2 = wp + 2.0f, w3 = wp + 3.0f;

    float4 o0, o1, o2;
    o0.x = fmaf(wc0, w0, base0);
    o0.y = fmaf(wc1, w0, base1);
    o0.z = fmaf(wc2, w0, base2);
    o0.w = fmaf(wc0, w1, base0);

    o1.x = fmaf(wc1, w1, base1);
    o1.y = fmaf(wc2, w1, base2);
    o1.z = fmaf(wc0, w2, base0);
    o1.w = fmaf(wc1, w2, base1);

    o2.x = fmaf(wc2, w2, base2);
    o2.y = fmaf(wc0, w3, base0);
    o2.z = fmaf(wc1, w3, base1);
    o2.w = fmaf(wc2, w3, base2);

    // smem float4 slots 3t, 3t+1, 3t+2 (48B stride; conflict-free in 8-lane phases)
    s[3u * t + 0u] = o0;
    s[3u * t + 1u] = o1;
    s[3u * t + 2u] = o2;

    __syncthreads();

    // ---- Phase 2: coalesced copy to gmem ----
    float4* dst = out4 + (size_t)blockIdx.x * BLK_F4;
    dst[t]        = s[t];
    dst[t + 224u] = s[t + 224u];
    dst[t + 448u] = s[t + 448u];
}

extern "C" void kernel_launch(void* const* d_in, const int* in_sizes, int n_in,
                              void* d_out, int out_size) {
    const float* mat = (const float*)d_in[0];
    float4* out4 = (float4*)d_out;
    affine_shift_kernel<<<NBLOCKS, THREADS>>>(mat, out4);
}